// round 7
// baseline (speedup 1.0000x reference)
#include <cuda_runtime.h>
#include <math.h>

#define N_NODES 10000
#define N_EDGES 200000

// ---- output offsets (pytree leaf order) ----
#define OFF_X     0
#define OFF_LOSS  40000
#define OFF_BETA  40001
#define OFF_RES   40002
#define OFF_X1    240002
#define OFF_X2    1520002
#define OFF_X3    2800002
#define OFF_X4    4080002
#define OFF_E1    5360002
#define OFF_E2    30960002
#define OFF_E3    56560002
#define OFF_E4    82160002

// ---- scratch ----
__device__ float g_xsum[N_NODES * 128];   // zero-init at load; invariant: zero after each launch
__device__ int   g_cnt[N_NODES];
__device__ float g_loss[1];
__device__ float g_nf_t[N_NODES * 128];
__device__ float g_ef_t[N_EDGES * 128];
__device__ float g_side[N_EDGES * 32];    // [eam(4) | zeros] tf32, edge-major
__device__ float g_nside[N_NODES * 32];   // [xorg(4) | zeros] tf32, node-major
__device__ float g_x1t[N_NODES * 128];
__device__ float g_x2t[N_NODES * 128];
__device__ float g_x3t[N_NODES * 128];
__device__ float g_e1t[N_EDGES * 128];
__device__ float g_e2t[N_EDGES * 128];
__device__ float g_e3t[N_EDGES * 128];
__device__ float g_Yr[N_NODES * 128];     // node-row partial
__device__ float g_Yc[N_NODES * 128];     // node-col partial
// permuted tf32 weights: 76 chunks x 4096 floats
__device__ float g_PW[76 * 4096];

__device__ __forceinline__ unsigned f2tf32(float f) {
    unsigned u;
    asm("cvt.rna.tf32.f32 %0, %1;" : "=r"(u) : "f"(f));
    return u;
}
__device__ __forceinline__ float tf32f(float f) { return __uint_as_float(f2tf32(f)); }

__device__ __forceinline__ void qmul4(float qw,float qx,float qy,float qz,
                                      float rw,float rx,float ry,float rz,
                                      float& ow,float& ox,float& oy,float& oz) {
    ow = qw*rw - qx*rx - qy*ry - qz*rz;
    ox = qw*rx + qx*rw + qy*rz - qz*ry;
    oy = qw*ry - qx*rz + qy*rw + qz*rx;
    oz = qw*rz + qx*ry - qy*rx + qz*rw;
}

// ---------------- small kernels ----------------
__global__ void zero_f(float* p, int n) {
    int i = blockIdx.x * blockDim.x + threadIdx.x;
    if (i < n) p[i] = 0.f;
}
__global__ void zero_i(int* p, int n) {
    int i = blockIdx.x * blockDim.x + threadIdx.x;
    if (i < n) p[i] = 0;
}
__global__ void conv_tf32(const float* __restrict__ in, float* __restrict__ out, int n) {
    int i = blockIdx.x * blockDim.x + threadIdx.x;
    if (i < n) out[i] = tf32f(in[i]);
}

// permW: map W rows into per-GEMM chunked fragment order.
// chunk layout (4096 floats): idx = (((wn*4+ks)*4+q)*32+lane)*4+elem
//   kp = ch*32 + ks*8 + tg + (elem&1)*4 ; n = wn*64 + (2q+(elem>>1))*8 + g
struct PermParams { int dst[4]; int src[4]; int len[4]; int nseg; int nCh; };
__global__ void permW_kernel(const float* __restrict__ W, float* __restrict__ PW,
                             PermParams pp) {
    int o = blockIdx.x * blockDim.x + threadIdx.x;
    if (o >= pp.nCh * 4096) return;
    int ch = o >> 12, r = o & 4095;
    int wn = r >> 11, r2 = r & 2047;
    int ks = r2 >> 9, r3 = r2 & 511;
    int q  = r3 >> 7, r4 = r3 & 127;
    int lane = r4 >> 2, elem = r4 & 3;
    int g = lane >> 2, tg = lane & 3;
    int kp = ch*32 + ks*8 + tg + (elem & 1)*4;
    int n  = wn*64 + (2*q + (elem >> 1))*8 + g;
    float v = 0.f;
#pragma unroll
    for (int s = 0; s < 4; s++) {
        if (s < pp.nseg && kp >= pp.dst[s] && kp < pp.dst[s] + pp.len[s]) {
            v = tf32f(W[(size_t)(pp.src[s] + kp - pp.dst[s]) * 128 + n]);
            break;
        }
    }
    PW[o] = v;
}

// side table (eam per edge) + row counts
__global__ void prep_kernel(const float* __restrict__ x_org,
                            const float* __restrict__ edge_attr,
                            const int* __restrict__ row,
                            const int* __restrict__ col,
                            float* __restrict__ side,
                            int* __restrict__ cnt) {
    int e = blockIdx.x * blockDim.x + threadIdx.x;
    if (e >= N_EDGES) return;
    int r = row[e], c = col[e];
    float cw = x_org[c*4+0], cx = -x_org[c*4+1], cy = -x_org[c*4+2], cz = -x_org[c*4+3];
    float aw = edge_attr[e*4+0], ax = edge_attr[e*4+1], ay = edge_attr[e*4+2], az = edge_attr[e*4+3];
    float tw,tx,ty,tz;
    qmul4(cw,cx,cy,cz, aw,ax,ay,az, tw,tx,ty,tz);
    float rw = x_org[r*4+0], rx = x_org[r*4+1], ry = x_org[r*4+2], rz = x_org[r*4+3];
    float ow,ox,oy,oz;
    qmul4(tw,tx,ty,tz, rw,rx,ry,rz, ow,ox,oy,oz);
    float* s = side + (size_t)e * 32;
    s[0]=tf32f(ow); s[1]=tf32f(ox); s[2]=tf32f(oy); s[3]=tf32f(oz);
#pragma unroll
    for (int i = 4; i < 32; i++) s[i] = 0.f;
    atomicAdd(&cnt[r], 1);
}

// nside table (xorg per node, tf32)
__global__ void prep_nodes(const float* __restrict__ x_org, float* __restrict__ nside) {
    int n = blockIdx.x * blockDim.x + threadIdx.x;
    if (n >= N_NODES) return;
    float* s = nside + (size_t)n * 32;
    s[0]=tf32f(x_org[n*4+0]); s[1]=tf32f(x_org[n*4+1]);
    s[2]=tf32f(x_org[n*4+2]); s[3]=tf32f(x_org[n*4+3]);
#pragma unroll
    for (int i = 4; i < 32; i++) s[i] = 0.f;
}

// ---------------- generic contiguous-A tf32 GEMM ----------------
struct Stage { const float* tab; int widthF; int strideF; int nCh; };
struct GP {
    Stage st[2]; int nSt; int totCh;
    const float* PW;
    const float* bias;
    const float* Yr; const float* Yc;
    float* e_out; float* et; float* xsum;
    const int* row; const int* col;
    int nRows;
    float* Yout;   // non-null => node mode (store partials, no bias/relu/atomics)
};

#define BM 128
#define A_BUF_F 16896     // 128 * 132
#define B_BUF_F 4096
#define SMEM_FLOATS (2*A_BUF_F + 2*B_BUF_F)
#define SMEM_BYTES  (SMEM_FLOATS*4 + 32)

__device__ __forceinline__ void bulk_g2s(unsigned dst, const float* src, unsigned bytes,
                                         unsigned mbar) {
    asm volatile(
        "cp.async.bulk.shared::cluster.global.mbarrier::complete_tx::bytes [%0], [%1], %2, [%3];"
        :: "r"(dst), "l"(src), "r"(bytes), "r"(mbar) : "memory");
}
__device__ __forceinline__ void mbar_init(unsigned mbar, unsigned cnt) {
    asm volatile("mbarrier.init.shared.b64 [%0], %1;" :: "r"(mbar), "r"(cnt) : "memory");
}
__device__ __forceinline__ void mbar_expect(unsigned mbar, unsigned bytes) {
    asm volatile("mbarrier.arrive.expect_tx.shared.b64 _, [%0], %1;"
                 :: "r"(mbar), "r"(bytes) : "memory");
}
__device__ __forceinline__ void mbar_wait(unsigned mbar, unsigned parity) {
    asm volatile(
        "{\n\t.reg .pred P;\n\t"
        "WAIT_%=:\n\t"
        "mbarrier.try_wait.parity.acquire.cta.shared::cta.b64 P, [%0], %1, 0x989680;\n\t"
        "@P bra.uni DONE_%=;\n\t"
        "bra.uni WAIT_%=;\n\t"
        "DONE_%=:\n\t}"
        :: "r"(mbar), "r"(parity) : "memory");
}

__global__ void __launch_bounds__(256, 1)
gemm_k(const __grid_constant__ GP p) {
    extern __shared__ __align__(16) float smem[];
    float* Abuf[2] = { smem, smem + A_BUF_F };
    float* Bbuf[2] = { smem + 2*A_BUF_F, smem + 2*A_BUF_F + B_BUF_F };
    unsigned mbase = (unsigned)__cvta_generic_to_shared(smem + SMEM_FLOATS);
    unsigned mbA[2] = { mbase, mbase + 8 };
    unsigned mbB[2] = { mbase + 16, mbase + 24 };
    unsigned AbufU[2] = { (unsigned)__cvta_generic_to_shared(Abuf[0]),
                          (unsigned)__cvta_generic_to_shared(Abuf[1]) };
    unsigned BbufU[2] = { (unsigned)__cvta_generic_to_shared(Bbuf[0]),
                          (unsigned)__cvta_generic_to_shared(Bbuf[1]) };

    int tid = threadIdx.x;
    int lane = tid & 31, wrp = tid >> 5;
    int r_base = blockIdx.x * BM;

    if (tid == 0) {
        mbar_init(mbA[0], 1); mbar_init(mbA[1], 1);
        mbar_init(mbB[0], 1); mbar_init(mbB[1], 1);
    }
    __syncthreads();

    int wm = wrp & 3, wn = wrp >> 2;
    int m0 = wm * 32, nb = wn * 64;
    int g = lane >> 2, tg = lane & 3;

    float acc[2][8][4];
#pragma unroll
    for (int mt = 0; mt < 2; mt++)
#pragma unroll
        for (int j = 0; j < 8; j++)
#pragma unroll
            for (int c = 0; c < 4; c++) acc[mt][j][c] = 0.f;

    auto issueA = [&](int s) {
        if (tid < 128) {
            Stage st = p.st[s];
            int idx = min(r_base + tid, p.nRows - 1);
            bulk_g2s(AbufU[s] + (unsigned)(tid * st.strideF * 4),
                     st.tab + (size_t)idx * st.widthF, st.widthF * 4, mbA[s]);
            if (tid == 0) mbar_expect(mbA[s], 128u * st.widthF * 4);
        }
    };
    auto issueB = [&](int gc) {
        if (tid == 0) {
            bulk_g2s(BbufU[gc & 1], p.PW + (size_t)gc * 4096, 16384, mbB[gc & 1]);
            mbar_expect(mbB[gc & 1], 16384);
        }
    };
    auto compute = [&](const float* As, int strideF, int kkBase, const float* Bs) {
#pragma unroll
        for (int ks = 0; ks < 4; ks++) {
            int kk = kkBase + ks * 8;
            unsigned a[2][4];
#pragma unroll
            for (int mt = 0; mt < 2; mt++) {
                int r = m0 + mt * 16;
                a[mt][0] = __float_as_uint(As[(r + g    ) * strideF + kk + tg    ]);
                a[mt][1] = __float_as_uint(As[(r + g + 8) * strideF + kk + tg    ]);
                a[mt][2] = __float_as_uint(As[(r + g    ) * strideF + kk + tg + 4]);
                a[mt][3] = __float_as_uint(As[(r + g + 8) * strideF + kk + tg + 4]);
            }
#pragma unroll
            for (int q = 0; q < 4; q++) {
                float4 bv = *reinterpret_cast<const float4*>(
                    &Bs[(((wn*4 + ks)*4 + q)*32 + lane)*4]);
                unsigned b00 = __float_as_uint(bv.x), b01 = __float_as_uint(bv.y);
                unsigned b10 = __float_as_uint(bv.z), b11 = __float_as_uint(bv.w);
                int j0 = 2*q, j1 = 2*q + 1;
#pragma unroll
                for (int mt = 0; mt < 2; mt++) {
                    asm volatile(
                        "mma.sync.aligned.m16n8k8.row.col.f32.tf32.tf32.f32 "
                        "{%0,%1,%2,%3}, {%4,%5,%6,%7}, {%8,%9}, {%0,%1,%2,%3};"
                        : "+f"(acc[mt][j0][0]), "+f"(acc[mt][j0][1]),
                          "+f"(acc[mt][j0][2]), "+f"(acc[mt][j0][3])
                        : "r"(a[mt][0]), "r"(a[mt][1]), "r"(a[mt][2]), "r"(a[mt][3]),
                          "r"(b00), "r"(b01));
                    asm volatile(
                        "mma.sync.aligned.m16n8k8.row.col.f32.tf32.tf32.f32 "
                        "{%0,%1,%2,%3}, {%4,%5,%6,%7}, {%8,%9}, {%0,%1,%2,%3};"
                        : "+f"(acc[mt][j1][0]), "+f"(acc[mt][j1][1]),
                          "+f"(acc[mt][j1][2]), "+f"(acc[mt][j1][3])
                        : "r"(a[mt][0]), "r"(a[mt][1]), "r"(a[mt][2]), "r"(a[mt][3]),
                          "r"(b10), "r"(b11));
                }
            }
        }
    };

    issueA(0);
    if (p.nSt > 1) issueA(1);
    issueB(0);
    if (p.totCh > 1) issueB(1);

    int gc = 0;
    for (int s = 0; s < p.nSt; s++) {
        mbar_wait(mbA[s], 0);
        const float* As = Abuf[s];
        int strideF = p.st[s].strideF;
        int nc = p.st[s].nCh;
        for (int c = 0; c < nc; c++, gc++) {
            mbar_wait(mbB[gc & 1], (gc >> 1) & 1);
            compute(As, strideF, c * 32, Bbuf[gc & 1]);
            __syncthreads();
            if (gc + 2 < p.totCh) issueB(gc + 2);
        }
    }

    // ---- epilogue ----
    if (p.Yout) {
        // node mode: store raw partials
#pragma unroll
        for (int mt = 0; mt < 2; mt++) {
            int nA = r_base + m0 + mt * 16 + g;
            int nB = nA + 8;
            bool vA = nA < p.nRows, vB = nB < p.nRows;
#pragma unroll
            for (int j = 0; j < 8; j++) {
                int n = nb + j*8 + tg*2;
                if (vA) *reinterpret_cast<float2*>(&p.Yout[(size_t)nA*128 + n]) =
                    make_float2(acc[mt][j][0], acc[mt][j][1]);
                if (vB) *reinterpret_cast<float2*>(&p.Yout[(size_t)nB*128 + n]) =
                    make_float2(acc[mt][j][2], acc[mt][j][3]);
            }
        }
    } else {
        // edge mode: m = acc + bias + Yr[row] + Yc[col]; relu->e_out(+echo); atomics->xsum
#pragma unroll
        for (int mt = 0; mt < 2; mt++) {
            int eA = r_base + m0 + mt * 16 + g;
            int eB = eA + 8;
            bool vA = eA < N_EDGES, vB = eB < N_EDGES;
            int rA = vA ? p.row[eA] : 0, cA = vA ? p.col[eA] : 0;
            int rB = vB ? p.row[eB] : 0, cB = vB ? p.col[eB] : 0;
#pragma unroll
            for (int j = 0; j < 8; j++) {
                int n = nb + j*8 + tg*2;
                float b0 = p.bias[n], b1 = p.bias[n+1];
                if (vA) {
                    float2 yr = *reinterpret_cast<const float2*>(&p.Yr[(size_t)rA*128 + n]);
                    float2 yc = *reinterpret_cast<const float2*>(&p.Yc[(size_t)cA*128 + n]);
                    float m0v = acc[mt][j][0] + b0 + yr.x + yc.x;
                    float m1v = acc[mt][j][1] + b1 + yr.y + yc.y;
                    float o0 = fmaxf(m0v, 0.f), o1 = fmaxf(m1v, 0.f);
                    *reinterpret_cast<float2*>(&p.e_out[(size_t)eA*128 + n]) = make_float2(o0, o1);
                    if (p.et)
                        *reinterpret_cast<float2*>(&p.et[(size_t)eA*128 + n]) =
                            make_float2(tf32f(o0), tf32f(o1));
                    atomicAdd(&p.xsum[rA*128 + n    ], m0v);
                    atomicAdd(&p.xsum[rA*128 + n + 1], m1v);
                }
                if (vB) {
                    float2 yr = *reinterpret_cast<const float2*>(&p.Yr[(size_t)rB*128 + n]);
                    float2 yc = *reinterpret_cast<const float2*>(&p.Yc[(size_t)cB*128 + n]);
                    float m0v = acc[mt][j][2] + b0 + yr.x + yc.x;
                    float m1v = acc[mt][j][3] + b1 + yr.y + yc.y;
                    float o0 = fmaxf(m0v, 0.f), o1 = fmaxf(m1v, 0.f);
                    *reinterpret_cast<float2*>(&p.e_out[(size_t)eB*128 + n]) = make_float2(o0, o1);
                    if (p.et)
                        *reinterpret_cast<float2*>(&p.et[(size_t)eB*128 + n]) =
                            make_float2(tf32f(o0), tf32f(o1));
                    atomicAdd(&p.xsum[rB*128 + n    ], m0v);
                    atomicAdd(&p.xsum[rB*128 + n + 1], m1v);
                }
            }
        }
    }
}

// x_next = relu(xsum / max(cnt,1)); resets xsum; optional tf32 copy
__global__ void node_update(float* __restrict__ xsum,
                            const int* __restrict__ cnt,
                            float* __restrict__ xout,
                            float* __restrict__ xt, int n_elems) {
    int i = blockIdx.x * blockDim.x + threadIdx.x;
    if (i >= n_elems) return;
    int node = i >> 7;
    float c = (float)max(cnt[node], 1);
    float v = xsum[i];
    xsum[i] = 0.f;
    float x = fmaxf(v / c, 0.f);
    xout[i] = x;
    if (xt) xt[i] = tf32f(x);
}

__global__ void lin1_kernel(const float* __restrict__ x4,
                            const float* __restrict__ w,
                            const float* __restrict__ bb,
                            const float* __restrict__ x_org,
                            float* __restrict__ xout) {
    int n = blockIdx.x * blockDim.x + threadIdx.x;
    if (n >= N_NODES) return;
    float q0 = bb[0], q1 = bb[1], q2 = bb[2], q3 = bb[3];
    for (int k = 0; k < 128; k++) {
        float v = x4[(size_t)n * 128 + k];
        q0 = fmaf(v, w[k*4+0], q0);
        q1 = fmaf(v, w[k*4+1], q1);
        q2 = fmaf(v, w[k*4+2], q2);
        q3 = fmaf(v, w[k*4+3], q3);
    }
    float rw = x_org[n*4+0], rx = x_org[n*4+1], ry = x_org[n*4+2], rz = x_org[n*4+3];
    float ow,ox,oy,oz;
    qmul4(q0,q1,q2,q3, rw,rx,ry,rz, ow,ox,oy,oz);
    float nn = sqrtf(ow*ow + ox*ox + oy*oy + oz*oz);
    nn = fmaxf(nn, 1e-12f);
    xout[n*4+0] = ow/nn; xout[n*4+1] = ox/nn; xout[n*4+2] = oy/nn; xout[n*4+3] = oz/nn;
}

__global__ void loss_kernel(const float* __restrict__ gt,
                            const float* __restrict__ x,
                            const int* __restrict__ row,
                            const int* __restrict__ col,
                            const float* __restrict__ beta_p,
                            float* __restrict__ loss_acc) {
    int e = blockIdx.x * blockDim.x + threadIdx.x;
    float local = 0.f;
    if (e < N_EDGES) {
        int r = row[e], c = col[e];
        float aw = gt[c*4+0], ax = gt[c*4+1], ay = gt[c*4+2], az = gt[c*4+3];
        float bw = gt[r*4+0], bx = -gt[r*4+1], by = -gt[r*4+2], bz = -gt[r*4+3];
        float gw,gx,gy,gz;
        qmul4(aw,ax,ay,az, bw,bx,by,bz, gw,gx,gy,gz);
        float cw2 = x[c*4+0], cx2 = x[c*4+1], cy2 = x[c*4+2], cz2 = x[c*4+3];
        float dw = x[r*4+0], dx = -x[r*4+1], dy = -x[r*4+2], dz = -x[r*4+3];
        float xw,xx,xy,xz;
        qmul4(cw2,cx2,cy2,cz2, dw,dx,dy,dz, xw,xx,xy,xz);
        float lw,lx,ly,lz;
        qmul4(gw,-gx,-gy,-gz, xw,xx,xy,xz, lw,lx,ly,lz);
        float nn = sqrtf(lw*lw + lx*lx + ly*ly + lz*lz);
        nn = fmaxf(nn, 1e-12f);
        lw /= nn; lx /= nn; ly /= nn; lz /= nn;
        float beta = beta_p[0];
        float d[4] = {fabsf(lw - 1.f), fabsf(lx), fabsf(ly), fabsf(lz)};
#pragma unroll
        for (int i = 0; i < 4; i++) {
            float v = d[i];
            local += (v < beta) ? (0.5f * v * v / beta) : (v - 0.5f * beta);
        }
    }
    __shared__ float sm[256];
    sm[threadIdx.x] = local;
    __syncthreads();
    for (int s = 128; s > 0; s >>= 1) {
        if (threadIdx.x < s) sm[threadIdx.x] += sm[threadIdx.x + s];
        __syncthreads();
    }
    if (threadIdx.x == 0) atomicAdd(loss_acc, sm[0]);
}

__global__ void finalize_kernel(const float* __restrict__ loss_acc,
                                const float* __restrict__ beta_p,
                                float* __restrict__ out) {
    out[OFF_LOSS] = loss_acc[0] / (float)(N_EDGES * 4);
    out[OFF_BETA] = beta_p[0];
}

__global__ void outres_kernel(const float* __restrict__ e4,
                              const float* __restrict__ w,
                              const float* __restrict__ b,
                              float* __restrict__ out) {
    int gw = (blockIdx.x * blockDim.x + threadIdx.x) >> 5;
    int lane = threadIdx.x & 31;
    if (gw >= N_EDGES) return;
    float s = 0.f;
#pragma unroll
    for (int k = lane; k < 128; k += 32)
        s = fmaf(e4[(size_t)gw * 128 + k], w[k], s);
#pragma unroll
    for (int o = 16; o > 0; o >>= 1) s += __shfl_down_sync(0xFFFFFFFFu, s, o);
    if (lane == 0) out[OFF_RES + gw] = s + b[0];
}

// ---------------- host ----------------
extern "C" void kernel_launch(void* const* d_in, const int* in_sizes, int n_in,
                              void* d_out, int out_size) {
    const float* x_org     = (const float*)d_in[0];
    const float* edge_attr = (const float*)d_in[1];
    const float* gt_q      = (const float*)d_in[2];
    const float* beta      = (const float*)d_in[3];
    const float* node_feat = (const float*)d_in[4];
    const float* edge_feat = (const float*)d_in[5];
    const float* W1 = (const float*)d_in[6];
    const float* b1 = (const float*)d_in[7];
    const float* W2 = (const float*)d_in[8];
    const float* b2 = (const float*)d_in[9];
    const float* W3 = (const float*)d_in[10];
    const float* b3 = (const float*)d_in[11];
    const float* W4 = (const float*)d_in[12];
    const float* b4 = (const float*)d_in[13];
    const float* lin1_w = (const float*)d_in[14];
    const float* lin1_b = (const float*)d_in[15];
    const float* lin2_w = (const float*)d_in[16];
    const float* lin2_b = (const float*)d_in[17];
    const int* ei = (const int*)d_in[18];
    const int* row = ei;
    const int* col = ei + N_EDGES;

    float* out = (float*)d_out;
    float* x1 = out + OFF_X1;
    float* x2 = out + OFF_X2;
    float* x3 = out + OFF_X3;
    float* x4 = out + OFF_X4;
    float* e1 = out + OFF_E1;
    float* e2 = out + OFF_E2;
    float* e3 = out + OFF_E3;
    float* e4 = out + OFF_E4;

    float *xsum, *lossacc, *nf_t, *ef_t, *side, *nside;
    float *x1t, *x2t, *x3t, *e1t, *e2t, *e3t, *PW, *Yr, *Yc;
    int* cnt;
    cudaGetSymbolAddress((void**)&xsum, g_xsum);
    cudaGetSymbolAddress((void**)&lossacc, g_loss);
    cudaGetSymbolAddress((void**)&cnt, g_cnt);
    cudaGetSymbolAddress((void**)&nf_t, g_nf_t);
    cudaGetSymbolAddress((void**)&ef_t, g_ef_t);
    cudaGetSymbolAddress((void**)&side, g_side);
    cudaGetSymbolAddress((void**)&nside, g_nside);
    cudaGetSymbolAddress((void**)&x1t, g_x1t);
    cudaGetSymbolAddress((void**)&x2t, g_x2t);
    cudaGetSymbolAddress((void**)&x3t, g_x3t);
    cudaGetSymbolAddress((void**)&e1t, g_e1t);
    cudaGetSymbolAddress((void**)&e2t, g_e2t);
    cudaGetSymbolAddress((void**)&e3t, g_e3t);
    cudaGetSymbolAddress((void**)&PW, g_PW);
    cudaGetSymbolAddress((void**)&Yr, g_Yr);
    cudaGetSymbolAddress((void**)&Yc, g_Yc);

    cudaFuncSetAttribute(gemm_k, cudaFuncAttributeMaxDynamicSharedMemorySize, SMEM_BYTES);

    zero_i<<<(N_NODES + 255)/256, 256>>>(cnt, N_NODES);
    zero_f<<<1, 32>>>(lossacc, 1);
    prep_kernel<<<(N_EDGES + 255)/256, 256>>>(x_org, edge_attr, row, col, side, cnt);
    prep_nodes<<<(N_NODES + 255)/256, 256>>>(x_org, nside);
    conv_tf32<<<(N_NODES*128 + 255)/256, 256>>>(node_feat, nf_t, N_NODES*128);
    conv_tf32<<<(N_EDGES*128 + 255)/256, 256>>>(edge_feat, ef_t, N_EDGES*128);

    // ---- permuted weight chunks (76 total) ----
    // order: g1r(5) g1c(5) g1e(5) g2r(4) g2c(4) g2e(5) g3r(8) g3c(8) g3e(8) g4r(8) g4c(8) g4e(8)
    int pwo[13];
    {
        int counts[12] = {5,5,5,4,4,5,8,8,8,8,8,8};
        pwo[0] = 0;
        for (int i = 0; i < 12; i++) pwo[i+1] = pwo[i] + counts[i];
    }
    auto perm = [&](const float* W, int slot, int nseg,
                    int d0,int s0,int l0, int d1,int s1,int l1) {
        PermParams pp;
        pp.dst[0]=d0; pp.src[0]=s0; pp.len[0]=l0;
        pp.dst[1]=d1; pp.src[1]=s1; pp.len[1]=l1;
        pp.dst[2]=0; pp.src[2]=0; pp.len[2]=0;
        pp.dst[3]=0; pp.src[3]=0; pp.len[3]=0;
        pp.nseg=nseg; pp.nCh = pwo[slot+1]-pwo[slot];
        permW_kernel<<<(pp.nCh*4096 + 255)/256, 256>>>(W, PW + (size_t)pwo[slot]*4096, pp);
    };
    perm(W1, 0, 2, 0,0,128,   128,128,4);   // g1r: nf_r + xorg_r
    perm(W1, 1, 2, 0,132,128, 128,260,4);   // g1c: nf_c + xorg_c
    perm(W1, 2, 2, 0,264,128, 128,392,4);   // g1e: ef + eam
    perm(W2, 3, 1, 0,0,128,   0,0,0);       // g2r: x1_r
    perm(W2, 4, 1, 0,128,128, 0,0,0);       // g2c: x1_c
    perm(W2, 5, 2, 0,260,128, 128,256,4);   // g2e: e1 + eam
    perm(W3, 6, 1, 0,0,256,   0,0,0);       // g3r: x2_r,x1_r
    perm(W3, 7, 1, 0,256,256, 0,0,0);       // g3c
    perm(W3, 8, 1, 0,512,256, 0,0,0);       // g3e: e2,e1
    perm(W4, 9, 1, 0,0,256,   0,0,0);       // g4r
    perm(W4,10, 1, 0,256,256, 0,0,0);       // g4c
    perm(W4,11, 1, 0,512,256, 0,0,0);       // g4e

    const int EGRID = (N_EDGES + BM - 1) / BM;
    const int NGRID = (N_NODES + BM - 1) / BM;

    auto node_gemm = [&](int slot, const float* t0, const float* t1, float* Yout) {
        GP p{};
        p.st[0] = { t0, 128, 132, 4 };
        if (t1 == nside)      { p.st[1] = { t1, 32, 36, 1 };  p.nSt = 2; p.totCh = 5; }
        else if (t1)          { p.st[1] = { t1, 128, 132, 4 }; p.nSt = 2; p.totCh = 8; }
        else                  { p.nSt = 1; p.totCh = 4; }
        p.PW = PW + (size_t)pwo[slot]*4096;
        p.nRows = N_NODES; p.Yout = Yout;
        gemm_k<<<NGRID, 256, SMEM_BYTES>>>(p);
    };
    auto edge_gemm = [&](int slot, const float* t0, const float* t1, bool t1side,
                         const float* bias, float* e_out, float* et) {
        GP p{};
        p.st[0] = { t0, 128, 132, 4 };
        if (t1side) { p.st[1] = { t1, 32, 36, 1 };  p.nSt = 2; p.totCh = 5; }
        else        { p.st[1] = { t1, 128, 132, 4 }; p.nSt = 2; p.totCh = 8; }
        p.PW = PW + (size_t)pwo[slot]*4096;
        p.bias = bias; p.Yr = Yr; p.Yc = Yc;
        p.e_out = e_out; p.et = et; p.xsum = xsum;
        p.row = row; p.col = col;
        p.nRows = N_EDGES; p.Yout = nullptr;
        gemm_k<<<EGRID, 256, SMEM_BYTES>>>(p);
    };

    // Layer 1
    node_gemm(0, nf_t, nside, Yr);
    node_gemm(1, nf_t, nside, Yc);
    edge_gemm(2, ef_t, side, true, b1, e1, e1t);
    node_update<<<(N_NODES*128 + 255)/256, 256>>>(xsum, cnt, x1, x1t, N_NODES*128);
    // Layer 2
    node_gemm(3, x1t, nullptr, Yr);
    node_gemm(4, x1t, nullptr, Yc);
    edge_gemm(5, e1t, side, true, b2, e2, e2t);
    node_update<<<(N_NODES*128 + 255)/256, 256>>>(xsum, cnt, x2, x2t, N_NODES*128);
    // Layer 3
    node_gemm(6, x2t, x1t, Yr);
    node_gemm(7, x2t, x1t, Yc);
    edge_gemm(8, e2t, e1t, false, b3, e3, e3t);
    node_update<<<(N_NODES*128 + 255)/256, 256>>>(xsum, cnt, x3, x3t, N_NODES*128);
    // Layer 4
    node_gemm(9,  x3t, x2t, Yr);
    node_gemm(10, x3t, x2t, Yc);
    edge_gemm(11, e3t, e2t, false, b4, e4, nullptr);
    node_update<<<(N_NODES*128 + 255)/256, 256>>>(xsum, cnt, x4, nullptr, N_NODES*128);

    lin1_kernel<<<(N_NODES + 255)/256, 256>>>(x4, lin1_w, lin1_b, x_org, out + OFF_X);
    loss_kernel<<<(N_EDGES + 255)/256, 256>>>(gt_q, out + OFF_X, row, col, beta, lossacc);
    finalize_kernel<<<1, 1>>>(lossacc, beta, out);
    outres_kernel<<<(N_EDGES*32 + 255)/256, 256>>>(e4, lin2_w, lin2_b, out);

    (void)in_sizes; (void)n_in; (void)out_size;
}

// round 9
// speedup vs baseline: 1.1114x; 1.1114x over previous
#include <cuda_runtime.h>
#include <math.h>

#define N_NODES 10000
#define N_EDGES 200000

// ---- output offsets (pytree leaf order) ----
#define OFF_X     0
#define OFF_LOSS  40000
#define OFF_BETA  40001
#define OFF_RES   40002
#define OFF_X1    240002
#define OFF_X2    1520002
#define OFF_X3    2800002
#define OFF_X4    4080002
#define OFF_E1    5360002
#define OFF_E2    30960002
#define OFF_E3    56560002
#define OFF_E4    82160002

// ---- scratch ----
__device__ float g_xsum[N_NODES * 128];   // zero-init at load; invariant: zero after each launch
__device__ int   g_cnt[N_NODES];
__device__ float g_loss[1];
__device__ float g_side[N_EDGES * 32];    // [eam(4) | zeros] tf32, edge-major
__device__ float g_nside[N_NODES * 32];   // [xorg(4) | zeros] tf32, node-major
__device__ float g_Yr[N_NODES * 128];
__device__ float g_Yc[N_NODES * 128];
__device__ float g_PW[76 * 4096];         // permuted tf32 weights

__device__ __forceinline__ unsigned f2tf32(float f) {
    unsigned u;
    asm("cvt.rna.tf32.f32 %0, %1;" : "=r"(u) : "f"(f));
    return u;
}
__device__ __forceinline__ float tf32f(float f) { return __uint_as_float(f2tf32(f)); }

__device__ __forceinline__ void qmul4(float qw,float qx,float qy,float qz,
                                      float rw,float rx,float ry,float rz,
                                      float& ow,float& ox,float& oy,float& oz) {
    ow = qw*rw - qx*rx - qy*ry - qz*rz;
    ox = qw*rx + qx*rw + qy*rz - qz*ry;
    oy = qw*ry - qx*rz + qy*rw + qz*rx;
    oz = qw*rz + qx*ry - qy*rx + qz*rw;
}

// ---------------- small kernels ----------------
__global__ void zero_f(float* p, int n) {
    int i = blockIdx.x * blockDim.x + threadIdx.x;
    if (i < n) p[i] = 0.f;
}
__global__ void zero_i(int* p, int n) {
    int i = blockIdx.x * blockDim.x + threadIdx.x;
    if (i < n) p[i] = 0;
}

// side (eam, tf32) + nside (xorg, tf32) + row counts
__global__ void prep_kernel(const float* __restrict__ x_org,
                            const float* __restrict__ edge_attr,
                            const int* __restrict__ row,
                            const int* __restrict__ col,
                            float* __restrict__ side,
                            float* __restrict__ nside,
                            int* __restrict__ cnt) {
    int e = blockIdx.x * blockDim.x + threadIdx.x;
    if (e < N_NODES) {
        float* s = nside + (size_t)e * 32;
        s[0]=tf32f(x_org[e*4+0]); s[1]=tf32f(x_org[e*4+1]);
        s[2]=tf32f(x_org[e*4+2]); s[3]=tf32f(x_org[e*4+3]);
#pragma unroll
        for (int i = 4; i < 32; i++) s[i] = 0.f;
    }
    if (e >= N_EDGES) return;
    int r = row[e], c = col[e];
    float cw = x_org[c*4+0], cx = -x_org[c*4+1], cy = -x_org[c*4+2], cz = -x_org[c*4+3];
    float aw = edge_attr[e*4+0], ax = edge_attr[e*4+1], ay = edge_attr[e*4+2], az = edge_attr[e*4+3];
    float tw,tx,ty,tz;
    qmul4(cw,cx,cy,cz, aw,ax,ay,az, tw,tx,ty,tz);
    float rw = x_org[r*4+0], rx = x_org[r*4+1], ry = x_org[r*4+2], rz = x_org[r*4+3];
    float ow,ox,oy,oz;
    qmul4(tw,tx,ty,tz, rw,rx,ry,rz, ow,ox,oy,oz);
    float* s = side + (size_t)e * 32;
    s[0]=tf32f(ow); s[1]=tf32f(ox); s[2]=tf32f(oy); s[3]=tf32f(oz);
#pragma unroll
    for (int i = 4; i < 32; i++) s[i] = 0.f;
    atomicAdd(&cnt[r], 1);
}

// ---- single-launch weight permuter for all 12 sub-GEMMs (76 chunks) ----
// chunk layout (4096 floats): idx = (((wn*4+ks)*2+q)*32+lane)*4+elem
//   kp = ch*32 + ks*8 + tg + (elem&1)*4 ; n = wn*32 + (2q+(elem>>1))*8 + g
struct PermAll {
    const float* W[4];
    int chOff[13];
    int wsel[12];
    int nseg[12];
    int d0[12], s0[12], l0[12];
    int d1[12], s1[12], l1[12];
};
__global__ void permAll_kernel(const __grid_constant__ PermAll pp, float* __restrict__ PW) {
    int o = blockIdx.x * blockDim.x + threadIdx.x;
    if (o >= 76 * 4096) return;
    int gch = o >> 12, r = o & 4095;
    int slot = 0;
#pragma unroll
    for (int s = 0; s < 12; s++) if (gch >= pp.chOff[s+1]) slot = s + 1;
    int ch = gch - pp.chOff[slot];
    int wn = r >> 10, r2 = r & 1023;
    int ks = r2 >> 8, r3 = r2 & 255;
    int q  = r3 >> 7, r4 = r3 & 127;
    int lane = r4 >> 2, elem = r4 & 3;
    int g = lane >> 2, tg = lane & 3;
    int kp = ch*32 + ks*8 + tg + (elem & 1)*4;
    int n  = wn*32 + (2*q + (elem >> 1))*8 + g;
    const float* W = pp.W[pp.wsel[slot]];
    float v = 0.f;
    if (kp >= pp.d0[slot] && kp < pp.d0[slot] + pp.l0[slot])
        v = tf32f(W[(size_t)(pp.s0[slot] + kp - pp.d0[slot]) * 128 + n]);
    else if (pp.nseg[slot] > 1 && kp >= pp.d1[slot] && kp < pp.d1[slot] + pp.l1[slot])
        v = tf32f(W[(size_t)(pp.s1[slot] + kp - pp.d1[slot]) * 128 + n]);
    PW[o] = v;
}

// ---------------- contiguous-A tf32 GEMM (512 threads, in-fragment cvt) ----------------
// shiftF: 0 for 16B-aligned tables; 2 for d_out-resident tables (rows are 8 mod 16 bytes):
//   bulk src starts 2 floats early (16B-aligned), transfers widthF+4 floats, smem reads +2.
struct Stage { const float* tab; int widthF; int strideF; int nCh; int shiftF; };
struct GP {
    Stage st[2]; int nSt; int totCh;
    const float* PW;  const float* PW2;   // PW2 for gridDim.y=2 (node pairs)
    const float* bias;
    const float* Yr; const float* Yc;
    float* e_out; float* xsum;
    const int* row; const int* col;
    int nRows;
    float* Yout; float* Yout2;            // non-null => node mode
};

#define BM 128
#define A_BUF_F 16896     // 128 * 132
#define B_BUF_F 4096
#define SMEM_FLOATS (2*A_BUF_F + 2*B_BUF_F)
#define SMEM_BYTES  (SMEM_FLOATS*4 + 32)

__device__ __forceinline__ void bulk_g2s(unsigned dst, const float* src, unsigned bytes,
                                         unsigned mbar) {
    asm volatile(
        "cp.async.bulk.shared::cluster.global.mbarrier::complete_tx::bytes [%0], [%1], %2, [%3];"
        :: "r"(dst), "l"(src), "r"(bytes), "r"(mbar) : "memory");
}
__device__ __forceinline__ void mbar_init(unsigned mbar, unsigned cnt) {
    asm volatile("mbarrier.init.shared.b64 [%0], %1;" :: "r"(mbar), "r"(cnt) : "memory");
}
__device__ __forceinline__ void mbar_expect(unsigned mbar, unsigned bytes) {
    asm volatile("mbarrier.arrive.expect_tx.shared.b64 _, [%0], %1;"
                 :: "r"(mbar), "r"(bytes) : "memory");
}
__device__ __forceinline__ void mbar_wait(unsigned mbar, unsigned parity) {
    asm volatile(
        "{\n\t.reg .pred P;\n\t"
        "WAIT_%=:\n\t"
        "mbarrier.try_wait.parity.acquire.cta.shared::cta.b64 P, [%0], %1, 0x989680;\n\t"
        "@P bra.uni DONE_%=;\n\t"
        "bra.uni WAIT_%=;\n\t"
        "DONE_%=:\n\t}"
        :: "r"(mbar), "r"(parity) : "memory");
}

__global__ void __launch_bounds__(512, 1)
gemm_k(const __grid_constant__ GP p) {
    extern __shared__ __align__(16) float smem[];
    float* Abuf[2] = { smem, smem + A_BUF_F };
    float* Bbuf[2] = { smem + 2*A_BUF_F, smem + 2*A_BUF_F + B_BUF_F };
    unsigned mbase = (unsigned)__cvta_generic_to_shared(smem + SMEM_FLOATS);
    unsigned mbA[2] = { mbase, mbase + 8 };
    unsigned mbB[2] = { mbase + 16, mbase + 24 };
    unsigned AbufU[2] = { (unsigned)__cvta_generic_to_shared(Abuf[0]),
                          (unsigned)__cvta_generic_to_shared(Abuf[1]) };
    unsigned BbufU[2] = { (unsigned)__cvta_generic_to_shared(Bbuf[0]),
                          (unsigned)__cvta_generic_to_shared(Bbuf[1]) };

    const float* PW = blockIdx.y ? p.PW2 : p.PW;
    float* Yout = blockIdx.y ? p.Yout2 : p.Yout;

    int tid = threadIdx.x;
    int lane = tid & 31, wrp = tid >> 5;
    int r_base = blockIdx.x * BM;

    if (tid == 0) {
        mbar_init(mbA[0], 1); mbar_init(mbA[1], 1);
        mbar_init(mbB[0], 1); mbar_init(mbB[1], 1);
    }
    __syncthreads();

    // 16 warps: warp (wm, wn) does 32x32 at (wm*32, wn*32)
    int wm = wrp & 3, wn = wrp >> 2;
    int m0 = wm * 32, nb = wn * 32;
    int g = lane >> 2, tg = lane & 3;

    float acc[2][4][4];
#pragma unroll
    for (int mt = 0; mt < 2; mt++)
#pragma unroll
        for (int j = 0; j < 4; j++)
#pragma unroll
            for (int c = 0; c < 4; c++) acc[mt][j][c] = 0.f;

    auto issueA = [&](int s) {
        if (tid < 128) {
            Stage st = p.st[s];
            int idx = min(r_base + tid, p.nRows - 1);
            const float* src = st.tab + (size_t)idx * st.widthF - st.shiftF;
            unsigned bytes = (unsigned)(st.widthF + (st.shiftF ? 4 : 0)) * 4u;
            bulk_g2s(AbufU[s] + (unsigned)(tid * st.strideF * 4), src, bytes, mbA[s]);
            if (tid == 0) mbar_expect(mbA[s], 128u * bytes);
        }
    };
    auto issueB = [&](int gc) {
        if (tid == 0) {
            bulk_g2s(BbufU[gc & 1], PW + (size_t)gc * 4096, 16384, mbB[gc & 1]);
            mbar_expect(mbB[gc & 1], 16384);
        }
    };
    auto compute = [&](const float* As, int strideF, int kShift, int kkBase, const float* Bs) {
#pragma unroll
        for (int ks = 0; ks < 4; ks++) {
            int kk = kkBase + ks * 8 + kShift;
            unsigned a[2][4];
#pragma unroll
            for (int mt = 0; mt < 2; mt++) {
                int r = m0 + mt * 16;
                a[mt][0] = f2tf32(As[(r + g    ) * strideF + kk + tg    ]);
                a[mt][1] = f2tf32(As[(r + g + 8) * strideF + kk + tg    ]);
                a[mt][2] = f2tf32(As[(r + g    ) * strideF + kk + tg + 4]);
                a[mt][3] = f2tf32(As[(r + g + 8) * strideF + kk + tg + 4]);
            }
#pragma unroll
            for (int q = 0; q < 2; q++) {
                float4 bv = *reinterpret_cast<const float4*>(
                    &Bs[(((wn*4 + ks)*2 + q)*32 + lane)*4]);
                unsigned b00 = __float_as_uint(bv.x), b01 = __float_as_uint(bv.y);
                unsigned b10 = __float_as_uint(bv.z), b11 = __float_as_uint(bv.w);
                int j0 = 2*q, j1 = 2*q + 1;
#pragma unroll
                for (int mt = 0; mt < 2; mt++) {
                    asm volatile(
                        "mma.sync.aligned.m16n8k8.row.col.f32.tf32.tf32.f32 "
                        "{%0,%1,%2,%3}, {%4,%5,%6,%7}, {%8,%9}, {%0,%1,%2,%3};"
                        : "+f"(acc[mt][j0][0]), "+f"(acc[mt][j0][1]),
                          "+f"(acc[mt][j0][2]), "+f"(acc[mt][j0][3])
                        : "r"(a[mt][0]), "r"(a[mt][1]), "r"(a[mt][2]), "r"(a[mt][3]),
                          "r"(b00), "r"(b01));
                    asm volatile(
                        "mma.sync.aligned.m16n8k8.row.col.f32.tf32.tf32.f32 "
                        "{%0,%1,%2,%3}, {%4,%5,%6,%7}, {%8,%9}, {%0,%1,%2,%3};"
                        : "+f"(acc[mt][j1][0]), "+f"(acc[mt][j1][1]),
                          "+f"(acc[mt][j1][2]), "+f"(acc[mt][j1][3])
                        : "r"(a[mt][0]), "r"(a[mt][1]), "r"(a[mt][2]), "r"(a[mt][3]),
                          "r"(b10), "r"(b11));
                }
            }
        }
    };

    issueA(0);
    if (p.nSt > 1) issueA(1);
    issueB(0);
    if (p.totCh > 1) issueB(1);

    int gc = 0;
    for (int s = 0; s < p.nSt; s++) {
        mbar_wait(mbA[s], 0);
        const float* As = Abuf[s];
        int strideF = p.st[s].strideF;
        int kShift = p.st[s].shiftF;
        int nc = p.st[s].nCh;
        for (int c = 0; c < nc; c++, gc++) {
            mbar_wait(mbB[gc & 1], (gc >> 1) & 1);
            compute(As, strideF, kShift, c * 32, Bbuf[gc & 1]);
            __syncthreads();
            if (gc + 2 < p.totCh) issueB(gc + 2);
        }
    }

    // ---- epilogue ----
    if (Yout) {
#pragma unroll
        for (int mt = 0; mt < 2; mt++) {
            int nA = r_base + m0 + mt * 16 + g;
            int nB = nA + 8;
            bool vA = nA < p.nRows, vB = nB < p.nRows;
#pragma unroll
            for (int j = 0; j < 4; j++) {
                int n = nb + j*8 + tg*2;
                if (vA) *reinterpret_cast<float2*>(&Yout[(size_t)nA*128 + n]) =
                    make_float2(acc[mt][j][0], acc[mt][j][1]);
                if (vB) *reinterpret_cast<float2*>(&Yout[(size_t)nB*128 + n]) =
                    make_float2(acc[mt][j][2], acc[mt][j][3]);
            }
        }
    } else {
#pragma unroll
        for (int mt = 0; mt < 2; mt++) {
            int eA = r_base + m0 + mt * 16 + g;
            int eB = eA + 8;
            bool vA = eA < N_EDGES, vB = eB < N_EDGES;
            int rA = vA ? p.row[eA] : 0, cA = vA ? p.col[eA] : 0;
            int rB = vB ? p.row[eB] : 0, cB = vB ? p.col[eB] : 0;
#pragma unroll
            for (int j = 0; j < 4; j++) {
                int n = nb + j*8 + tg*2;
                float b0 = p.bias[n], b1 = p.bias[n+1];
                if (vA) {
                    float2 yr = *reinterpret_cast<const float2*>(&p.Yr[(size_t)rA*128 + n]);
                    float2 yc = *reinterpret_cast<const float2*>(&p.Yc[(size_t)cA*128 + n]);
                    float m0v = acc[mt][j][0] + b0 + yr.x + yc.x;
                    float m1v = acc[mt][j][1] + b1 + yr.y + yc.y;
                    *reinterpret_cast<float2*>(&p.e_out[(size_t)eA*128 + n]) =
                        make_float2(fmaxf(m0v, 0.f), fmaxf(m1v, 0.f));
                    atomicAdd(&p.xsum[rA*128 + n    ], m0v);
                    atomicAdd(&p.xsum[rA*128 + n + 1], m1v);
                }
                if (vB) {
                    float2 yr = *reinterpret_cast<const float2*>(&p.Yr[(size_t)rB*128 + n]);
                    float2 yc = *reinterpret_cast<const float2*>(&p.Yc[(size_t)cB*128 + n]);
                    float m0v = acc[mt][j][2] + b0 + yr.x + yc.x;
                    float m1v = acc[mt][j][3] + b1 + yr.y + yc.y;
                    *reinterpret_cast<float2*>(&p.e_out[(size_t)eB*128 + n]) =
                        make_float2(fmaxf(m0v, 0.f), fmaxf(m1v, 0.f));
                    atomicAdd(&p.xsum[rB*128 + n    ], m0v);
                    atomicAdd(&p.xsum[rB*128 + n + 1], m1v);
                }
            }
        }
    }
}

// x_next = relu(xsum / max(cnt,1)); resets xsum
__global__ void node_update(float* __restrict__ xsum,
                            const int* __restrict__ cnt,
                            float* __restrict__ xout, int n_elems) {
    int i = blockIdx.x * blockDim.x + threadIdx.x;
    if (i >= n_elems) return;
    int node = i >> 7;
    float c = (float)max(cnt[node], 1);
    float v = xsum[i];
    xsum[i] = 0.f;
    xout[i] = fmaxf(v / c, 0.f);
}

__global__ void lin1_kernel(const float* __restrict__ x4,
                            const float* __restrict__ w,
                            const float* __restrict__ bb,
                            const float* __restrict__ x_org,
                            float* __restrict__ xout) {
    int n = blockIdx.x * blockDim.x + threadIdx.x;
    if (n >= N_NODES) return;
    float q0 = bb[0], q1 = bb[1], q2 = bb[2], q3 = bb[3];
    for (int k = 0; k < 128; k++) {
        float v = x4[(size_t)n * 128 + k];
        q0 = fmaf(v, w[k*4+0], q0);
        q1 = fmaf(v, w[k*4+1], q1);
        q2 = fmaf(v, w[k*4+2], q2);
        q3 = fmaf(v, w[k*4+3], q3);
    }
    float rw = x_org[n*4+0], rx = x_org[n*4+1], ry = x_org[n*4+2], rz = x_org[n*4+3];
    float ow,ox,oy,oz;
    qmul4(q0,q1,q2,q3, rw,rx,ry,rz, ow,ox,oy,oz);
    float nn = sqrtf(ow*ow + ox*ox + oy*oy + oz*oz);
    nn = fmaxf(nn, 1e-12f);
    xout[n*4+0] = ow/nn; xout[n*4+1] = ox/nn; xout[n*4+2] = oy/nn; xout[n*4+3] = oz/nn;
}

__global__ void loss_kernel(const float* __restrict__ gt,
                            const float* __restrict__ x,
                            const int* __restrict__ row,
                            const int* __restrict__ col,
                            const float* __restrict__ beta_p,
                            float* __restrict__ loss_acc) {
    int e = blockIdx.x * blockDim.x + threadIdx.x;
    float local = 0.f;
    if (e < N_EDGES) {
        int r = row[e], c = col[e];
        float aw = gt[c*4+0], ax = gt[c*4+1], ay = gt[c*4+2], az = gt[c*4+3];
        float bw = gt[r*4+0], bx = -gt[r*4+1], by = -gt[r*4+2], bz = -gt[r*4+3];
        float gw,gx,gy,gz;
        qmul4(aw,ax,ay,az, bw,bx,by,bz, gw,gx,gy,gz);
        float cw2 = x[c*4+0], cx2 = x[c*4+1], cy2 = x[c*4+2], cz2 = x[c*4+3];
        float dw = x[r*4+0], dx = -x[r*4+1], dy = -x[r*4+2], dz = -x[r*4+3];
        float xw,xx,xy,xz;
        qmul4(cw2,cx2,cy2,cz2, dw,dx,dy,dz, xw,xx,xy,xz);
        float lw,lx,ly,lz;
        qmul4(gw,-gx,-gy,-gz, xw,xx,xy,xz, lw,lx,ly,lz);
        float nn = sqrtf(lw*lw + lx*lx + ly*ly + lz*lz);
        nn = fmaxf(nn, 1e-12f);
        lw /= nn; lx /= nn; ly /= nn; lz /= nn;
        float beta = beta_p[0];
        float d[4] = {fabsf(lw - 1.f), fabsf(lx), fabsf(ly), fabsf(lz)};
#pragma unroll
        for (int i = 0; i < 4; i++) {
            float v = d[i];
            local += (v < beta) ? (0.5f * v * v / beta) : (v - 0.5f * beta);
        }
    }
    __shared__ float sm[256];
    sm[threadIdx.x] = local;
    __syncthreads();
    for (int s = 128; s > 0; s >>= 1) {
        if (threadIdx.x < s) sm[threadIdx.x] += sm[threadIdx.x + s];
        __syncthreads();
    }
    if (threadIdx.x == 0) atomicAdd(loss_acc, sm[0]);
}

__global__ void finalize_kernel(const float* __restrict__ loss_acc,
                                const float* __restrict__ beta_p,
                                float* __restrict__ out) {
    out[OFF_LOSS] = loss_acc[0] / (float)(N_EDGES * 4);
    out[OFF_BETA] = beta_p[0];
}

__global__ void outres_kernel(const float* __restrict__ e4,
                              const float* __restrict__ w,
                              const float* __restrict__ b,
                              float* __restrict__ out) {
    int gw = (blockIdx.x * blockDim.x + threadIdx.x) >> 5;
    int lane = threadIdx.x & 31;
    if (gw >= N_EDGES) return;
    float s = 0.f;
#pragma unroll
    for (int k = lane; k < 128; k += 32)
        s = fmaf(e4[(size_t)gw * 128 + k], w[k], s);
#pragma unroll
    for (int o = 16; o > 0; o >>= 1) s += __shfl_down_sync(0xFFFFFFFFu, s, o);
    if (lane == 0) out[OFF_RES + gw] = s + b[0];
}

// ---------------- host ----------------
extern "C" void kernel_launch(void* const* d_in, const int* in_sizes, int n_in,
                              void* d_out, int out_size) {
    const float* x_org     = (const float*)d_in[0];
    const float* edge_attr = (const float*)d_in[1];
    const float* gt_q      = (const float*)d_in[2];
    const float* beta      = (const float*)d_in[3];
    const float* node_feat = (const float*)d_in[4];
    const float* edge_feat = (const float*)d_in[5];
    const float* W1 = (const float*)d_in[6];
    const float* b1 = (const float*)d_in[7];
    const float* W2 = (const float*)d_in[8];
    const float* b2 = (const float*)d_in[9];
    const float* W3 = (const float*)d_in[10];
    const float* b3 = (const float*)d_in[11];
    const float* W4 = (const float*)d_in[12];
    const float* b4 = (const float*)d_in[13];
    const float* lin1_w = (const float*)d_in[14];
    const float* lin1_b = (const float*)d_in[15];
    const float* lin2_w = (const float*)d_in[16];
    const float* lin2_b = (const float*)d_in[17];
    const int* ei = (const int*)d_in[18];
    const int* row = ei;
    const int* col = ei + N_EDGES;

    float* out = (float*)d_out;
    float* x1 = out + OFF_X1;
    float* x2 = out + OFF_X2;
    float* x3 = out + OFF_X3;
    float* x4 = out + OFF_X4;
    float* e1 = out + OFF_E1;
    float* e2 = out + OFF_E2;
    float* e3 = out + OFF_E3;
    float* e4 = out + OFF_E4;

    float *xsum, *lossacc, *side, *nside, *PW, *Yr, *Yc;
    int* cnt;
    cudaGetSymbolAddress((void**)&xsum, g_xsum);
    cudaGetSymbolAddress((void**)&lossacc, g_loss);
    cudaGetSymbolAddress((void**)&cnt, g_cnt);
    cudaGetSymbolAddress((void**)&side, g_side);
    cudaGetSymbolAddress((void**)&nside, g_nside);
    cudaGetSymbolAddress((void**)&PW, g_PW);
    cudaGetSymbolAddress((void**)&Yr, g_Yr);
    cudaGetSymbolAddress((void**)&Yc, g_Yc);

    cudaFuncSetAttribute(gemm_k, cudaFuncAttributeMaxDynamicSharedMemorySize, SMEM_BYTES);

    zero_i<<<(N_NODES + 255)/256, 256>>>(cnt, N_NODES);
    zero_f<<<1, 32>>>(lossacc, 1);
    prep_kernel<<<(N_EDGES + 255)/256, 256>>>(x_org, edge_attr, row, col, side, nside, cnt);

    // ---- one-shot weight permute (12 slots, 76 chunks) ----
    int pwo[13];
    {
        PermAll pp;
        pp.W[0]=W1; pp.W[1]=W2; pp.W[2]=W3; pp.W[3]=W4;
        int counts[12] = {5,5,5,4,4,5,8,8,8,8,8,8};
        pp.chOff[0] = 0;
        for (int i = 0; i < 12; i++) pp.chOff[i+1] = pp.chOff[i] + counts[i];
        for (int i = 0; i < 13; i++) pwo[i] = pp.chOff[i];
        auto setS = [&](int s, int w, int ns, int d0,int s0,int l0, int d1,int s1,int l1) {
            pp.wsel[s]=w; pp.nseg[s]=ns;
            pp.d0[s]=d0; pp.s0[s]=s0; pp.l0[s]=l0;
            pp.d1[s]=d1; pp.s1[s]=s1; pp.l1[s]=l1;
        };
        setS(0, 0, 2, 0,0,128,   128,128,4);   // g1r: nf_r + xorg_r
        setS(1, 0, 2, 0,132,128, 128,260,4);   // g1c: nf_c + xorg_c
        setS(2, 0, 2, 0,264,128, 128,392,4);   // g1e: ef + eam
        setS(3, 1, 1, 0,0,128,   0,0,0);       // g2r
        setS(4, 1, 1, 0,128,128, 0,0,0);       // g2c
        setS(5, 1, 2, 0,260,128, 128,256,4);   // g2e: e1 + eam
        setS(6, 2, 1, 0,0,256,   0,0,0);       // g3r
        setS(7, 2, 1, 0,256,256, 0,0,0);       // g3c
        setS(8, 2, 1, 0,512,256, 0,0,0);       // g3e
        setS(9, 3, 1, 0,0,256,   0,0,0);       // g4r
        setS(10,3, 1, 0,256,256, 0,0,0);       // g4c
        setS(11,3, 1, 0,512,256, 0,0,0);       // g4e
        permAll_kernel<<<(76*4096 + 255)/256, 256>>>(pp, PW);
    }

    const int EGRID = (N_EDGES + BM - 1) / BM;
    const int NGRID = (N_NODES + BM - 1) / BM;

    // shift=2 for d_out-resident tables (8 mod 16 byte rows), 0 otherwise
    auto node_pair = [&](int slotR, int slotC, const float* t0, int sh0,
                         const float* t1, int sh1, bool t1side) {
        GP p{};
        p.st[0] = { t0, 128, 132, 4, sh0 };
        if (t1side)   { p.st[1] = { t1, 32, 36, 1, 0 };    p.nSt = 2; p.totCh = 5; }
        else if (t1)  { p.st[1] = { t1, 128, 132, 4, sh1 }; p.nSt = 2; p.totCh = 8; }
        else          { p.nSt = 1; p.totCh = 4; }
        p.PW  = PW + (size_t)pwo[slotR]*4096;
        p.PW2 = PW + (size_t)pwo[slotC]*4096;
        p.nRows = N_NODES; p.Yout = Yr; p.Yout2 = Yc;
        gemm_k<<<dim3(NGRID, 2), 512, SMEM_BYTES>>>(p);
    };
    auto edge_gemm = [&](int slot, const float* t0, int sh0, const float* t1, int sh1,
                         bool t1side, const float* bias, float* e_out) {
        GP p{};
        p.st[0] = { t0, 128, 132, 4, sh0 };
        if (t1side) { p.st[1] = { t1, 32, 36, 1, 0 };    p.nSt = 2; p.totCh = 5; }
        else        { p.st[1] = { t1, 128, 132, 4, sh1 }; p.nSt = 2; p.totCh = 8; }
        p.PW = PW + (size_t)pwo[slot]*4096; p.PW2 = p.PW;
        p.bias = bias; p.Yr = Yr; p.Yc = Yc;
        p.e_out = e_out; p.xsum = xsum;
        p.row = row; p.col = col;
        p.nRows = N_EDGES; p.Yout = nullptr; p.Yout2 = nullptr;
        gemm_k<<<EGRID, 512, SMEM_BYTES>>>(p);
    };
    auto upd = [&](float* xout) {
        node_update<<<(N_NODES*128 + 255)/256, 256>>>(xsum, cnt, xout, N_NODES*128);
    };

    // Layer 1
    node_pair(0, 1, node_feat, 0, nside, 0, true);
    edge_gemm(2, edge_feat, 0, side, 0, true, b1, e1);
    upd(x1);
    // Layer 2
    node_pair(3, 4, x1, 2, nullptr, 0, false);
    edge_gemm(5, e1, 2, side, 0, true, b2, e2);
    upd(x2);
    // Layer 3
    node_pair(6, 7, x2, 2, x1, 2, false);
    edge_gemm(8, e2, 2, e1, 2, false, b3, e3);
    upd(x3);
    // Layer 4
    node_pair(9, 10, x3, 2, x2, 2, false);
    edge_gemm(11, e3, 2, e2, 2, false, b4, e4);
    upd(x4);

    lin1_kernel<<<(N_NODES + 255)/256, 256>>>(x4, lin1_w, lin1_b, x_org, out + OFF_X);
    loss_kernel<<<(N_EDGES + 255)/256, 256>>>(gt_q, out + OFF_X, row, col, beta, lossacc);
    finalize_kernel<<<1, 1>>>(lossacc, beta, out);
    outres_kernel<<<(N_EDGES*32 + 255)/256, 256>>>(e4, lin2_w, lin2_b, out);

    (void)in_sizes; (void)n_in; (void)out_size;
}